// round 2
// baseline (speedup 1.0000x reference)
#include <cuda_runtime.h>

// TripletEntropyLoss: N=8192, D=128 fp32.
// loss = mean(relu(log(rowsum_i) - pos_sim_i))
//   rowsum_i = sum_j 0.5*exp(a_i.neg_j/4) + 0.25*exp(m(a_i.pos_j)/4) + 0.25*exp(m(a_i.a_j)/4)
//   m(.) masks the diagonal (j==i) to DELTA *before* exp — MUST be done in-epilogue
//   (the a_i.a_i term is exp(32)~8e13 and would destroy fp32 accuracy otherwise).
//   pos_sim_i = (a_i . p_i)/4.

#define NROWS 8192
#define DDIM  128

#define BM 128
#define BN 128
#define BK 16

__device__ float g_rowsum[NROWS];

__global__ __launch_bounds__(256) void zero_k(float* out) {
    int i = blockIdx.x * 256 + threadIdx.x;
    g_rowsum[i] = 0.0f;
    if (i == 0) out[0] = 0.0f;
}

__global__ __launch_bounds__(256) void gemm_exp_k(const float* __restrict__ A,
                                                  const float* __restrict__ P,
                                                  const float* __restrict__ Ng) {
    const float INV_MAG = 0.25f;
    const float DELTA_C = 0.001f;

    int rt = blockIdx.x;          // 64 row tiles
    int ct = blockIdx.y;          // 192 col tiles (3 matrices x 64)
    int m  = ct >> 6;             // 0 = negatives, 1 = positives, 2 = anchors
    const float* B = (m == 0) ? Ng : ((m == 1) ? P : A);
    float coef = (m == 0) ? 0.5f : 0.25f;

    int row0 = rt * BM;
    int col0 = (ct & 63) * BN;

    __shared__ float As[BK][BM];
    __shared__ float Bs[BK][BN];

    int tid = threadIdx.x;
    int tx  = tid & 15;           // 16 cols of threads
    int ty  = tid >> 4;           // 16 rows of threads
    int lr  = tid >> 1;           // load row within tile (0..127)
    int lc  = (tid & 1) * 8;      // load col offset within BK (0 or 8)

    float acc[8][8];
#pragma unroll
    for (int i = 0; i < 8; i++)
#pragma unroll
        for (int j = 0; j < 8; j++) acc[i][j] = 0.0f;

    const float* Abase = A + (size_t)(row0 + lr) * DDIM + lc;
    const float* Bbase = B + (size_t)(col0 + lr) * DDIM + lc;

    for (int kt = 0; kt < DDIM; kt += BK) {
        float4 a0 = *(const float4*)(Abase + kt);
        float4 a1 = *(const float4*)(Abase + kt + 4);
        float4 b0 = *(const float4*)(Bbase + kt);
        float4 b1 = *(const float4*)(Bbase + kt + 4);

        As[lc + 0][lr] = a0.x; As[lc + 1][lr] = a0.y;
        As[lc + 2][lr] = a0.z; As[lc + 3][lr] = a0.w;
        As[lc + 4][lr] = a1.x; As[lc + 5][lr] = a1.y;
        As[lc + 6][lr] = a1.z; As[lc + 7][lr] = a1.w;

        Bs[lc + 0][lr] = b0.x; Bs[lc + 1][lr] = b0.y;
        Bs[lc + 2][lr] = b0.z; Bs[lc + 3][lr] = b0.w;
        Bs[lc + 4][lr] = b1.x; Bs[lc + 5][lr] = b1.y;
        Bs[lc + 6][lr] = b1.z; Bs[lc + 7][lr] = b1.w;

        __syncthreads();

#pragma unroll
        for (int k = 0; k < BK; k++) {
            float a[8], b[8];
            *(float4*)(a)     = *(const float4*)(&As[k][ty * 8]);
            *(float4*)(a + 4) = *(const float4*)(&As[k][ty * 8 + 4]);
            *(float4*)(b)     = *(const float4*)(&Bs[k][tx * 8]);
            *(float4*)(b + 4) = *(const float4*)(&Bs[k][tx * 8 + 4]);
#pragma unroll
            for (int i = 0; i < 8; i++)
#pragma unroll
                for (int j = 0; j < 8; j++)
                    acc[i][j] = fmaf(a[i], b[j], acc[i][j]);
        }
        __syncthreads();
    }

    // Epilogue: exp, diagonal masking, per-row reduction, atomic accumulate.
    // Diagonal can only occur when the row tile and col tile cover the same
    // index range (tiles are aligned/same-size) and we're in P or A matrix.
    bool maybe_diag = (m >= 1) && (row0 == col0);

#pragma unroll
    for (int i = 0; i < 8; i++) {
        int gi = row0 + ty * 8 + i;
        float rs = 0.0f;
#pragma unroll
        for (int j = 0; j < 8; j++) {
            float v = acc[i][j];
            if (maybe_diag && (col0 + tx * 8 + j) == gi) v = DELTA_C;
            rs += __expf(v * INV_MAG);
        }
        // reduce across the 16 threads (tx) that share this row
#pragma unroll
        for (int off = 8; off > 0; off >>= 1)
            rs += __shfl_down_sync(0xffffffffu, rs, off, 16);
        if (tx == 0) atomicAdd(&g_rowsum[gi], coef * rs);
    }
}

__global__ __launch_bounds__(256) void finalize_k(const float* __restrict__ A,
                                                   const float* __restrict__ P,
                                                   float* out) {
    int tid = threadIdx.x;
    int row = blockIdx.x * 256 + tid;

    const float4* a4 = (const float4*)(A + (size_t)row * DDIM);
    const float4* p4 = (const float4*)(P + (size_t)row * DDIM);
    float d = 0.0f;
#pragma unroll
    for (int k = 0; k < DDIM / 4; k++) {
        float4 a = a4[k], p = p4[k];
        d += a.x * p.x + a.y * p.y + a.z * p.z + a.w * p.w;
    }
    float v = logf(g_rowsum[row]) - d * 0.25f;
    v = v > 0.0f ? v : 0.0f;

    __shared__ float sh[256];
    sh[tid] = v;
    __syncthreads();
#pragma unroll
    for (int s = 128; s > 0; s >>= 1) {
        if (tid < s) sh[tid] += sh[tid + s];
        __syncthreads();
    }
    if (tid == 0) atomicAdd(out, sh[0] * (1.0f / NROWS));
}

extern "C" void kernel_launch(void* const* d_in, const int* in_sizes, int n_in,
                              void* d_out, int out_size) {
    const float* A  = (const float*)d_in[0];  // anchors   [8192,128]
    const float* P  = (const float*)d_in[1];  // positives [8192,128]
    const float* Ng = (const float*)d_in[2];  // negatives [8192,128]
    float* out = (float*)d_out;

    zero_k<<<NROWS / 256, 256>>>(out);

    dim3 grid(NROWS / BM, 3 * NROWS / BN);   // (64, 192)
    gemm_exp_k<<<grid, 256>>>(A, P, Ng);

    finalize_k<<<NROWS / 256, 256>>>(A, P, out);
}

// round 5
// speedup vs baseline: 6.4384x; 6.4384x over previous
#include <cuda_runtime.h>
#include <cuda_bf16.h>
#include <cstdint>

// TripletEntropyLoss N=8192 D=128 — mma.sync bf16 tensor-core version
// (harness compiles at .target sm_100: no tcgen05; mma.sync.m16n8k16 is arch-agnostic).
// rowsum_i = sum_j 0.5*exp(a.n/4) + 0.25*exp(mask(a.p)/4) + 0.25*exp(mask(a.a)/4)
// loss = mean(relu(log(rowsum) - (a_i.p_i)/4)); pos_sim kept fully fp32.

#define NROWS 8192
#define DDIM  128
#define TILE  128
#define THREADS 256

#define DELTA_C 0.001f
#define INV_MAG 0.25f

__device__ float g_rowsum[NROWS];
__device__ __nv_bfloat16 g_Abf[NROWS * DDIM];
__device__ __nv_bfloat16 g_Pbf[NROWS * DDIM];
__device__ __nv_bfloat16 g_Nbf[NROWS * DDIM];

__device__ __forceinline__ uint32_t smem_u32(const void* p) {
    uint32_t a;
    asm("{ .reg .u64 t; cvta.to.shared.u64 t, %1; cvt.u32.u64 %0, t; }" : "=r"(a) : "l"(p));
    return a;
}

#define LDSM_X4(r0, r1, r2, r3, a) \
    asm volatile("ldmatrix.sync.aligned.m8n8.x4.shared.b16 {%0,%1,%2,%3}, [%4];" \
                 : "=r"(r0), "=r"(r1), "=r"(r2), "=r"(r3) : "r"(a))

#define MMA_BF16(d, a, b) \
    asm volatile("mma.sync.aligned.m16n8k16.row.col.f32.bf16.bf16.f32 " \
                 "{%0,%1,%2,%3}, {%4,%5,%6,%7}, {%8,%9}, {%0,%1,%2,%3};" \
                 : "+f"((d)[0]), "+f"((d)[1]), "+f"((d)[2]), "+f"((d)[3]) \
                 : "r"((a)[0]), "r"((a)[1]), "r"((a)[2]), "r"((a)[3]), \
                   "r"((b)[0]), "r"((b)[1]))

// ---------------- small kernels ----------------
__global__ __launch_bounds__(256) void zero_k(float* out) {
    int i = blockIdx.x * 256 + threadIdx.x;
    g_rowsum[i] = 0.0f;
    if (i == 0) out[0] = 0.0f;
}

__global__ __launch_bounds__(256) void conv_k(const float* __restrict__ A,
                                              const float* __restrict__ P,
                                              const float* __restrict__ Ng) {
    int m = blockIdx.y;
    const float* s = (m == 0) ? Ng : ((m == 1) ? P : A);
    __nv_bfloat16* d = (m == 0) ? g_Nbf : ((m == 1) ? g_Pbf : g_Abf);
    int i = (blockIdx.x * 256 + threadIdx.x) * 4;
    float4 v = *(const float4*)(s + i);
    __nv_bfloat162* d2 = (__nv_bfloat162*)(d + i);
    d2[0] = __floats2bfloat162_rn(v.x, v.y);
    d2[1] = __floats2bfloat162_rn(v.z, v.w);
}

// ---------------- main GEMM+exp kernel ----------------
// smem tile layout: row r (128 rows), 16 chunks of 16B per row (256B/row);
// chunk c stored at c ^ (r & 7) -> conflict-free LDSM and near-conflict-free STS.
__global__ __launch_bounds__(THREADS, 2) void gemm_exp_mma() {
    extern __shared__ char smem[];
    char* sA = smem;
    char* sB = smem + TILE * 256;

    int tid  = threadIdx.x;
    int lane = tid & 31;
    int wid  = tid >> 5;
    int wm   = wid >> 2;           // 0..1 : warp row group (64 rows)
    int wn   = wid & 3;            // 0..3 : warp col group (32 cols)

    int mat  = blockIdx.z;         // 0=Neg, 1=Pos, 2=Anc
    int row0 = blockIdx.x * TILE;
    int col0 = blockIdx.y * TILE;
    const __nv_bfloat16* Bsrc = (mat == 0) ? g_Nbf : ((mat == 1) ? g_Pbf : g_Abf);
    float coef = (mat == 0) ? 0.5f : 0.25f;

    // ---- global -> shared (swizzled) ----
#pragma unroll
    for (int it = 0; it < 8; it++) {
        int i = tid + it * 256;            // 2048 uint4
        int r = i >> 4, c = i & 15;
        uint4 va = *(const uint4*)(g_Abf + (size_t)(row0 + r) * DDIM + c * 8);
        *(uint4*)(sA + r * 256 + ((c ^ (r & 7)) << 4)) = va;
        uint4 vb = *(const uint4*)(Bsrc + (size_t)(col0 + r) * DDIM + c * 8);
        *(uint4*)(sB + r * 256 + ((c ^ (r & 7)) << 4)) = vb;
    }
    __syncthreads();

    // ---- fragment address precompute ----
    uint32_t sAu = smem_u32(sA);
    uint32_t sBu = smem_u32(sB);

    // A (ldmatrix.x4, one m16k16 tile): lanes 0-15 -> rows 0-15 (k lo chunk),
    // lanes 16-31 -> rows 0-15 (k hi chunk).
    int rA    = wm * 64 + (lane & 15);
    int halfA = lane >> 4;
    int a7    = rA & 7;
    uint32_t aBase[4];
#pragma unroll
    for (int mt = 0; mt < 4; mt++) aBase[mt] = sAu + (uint32_t)((rA + mt * 16) * 256);

    // B (ldmatrix.x4 covers two n8k16 tiles): mat index mm = lane>>3;
    // nt = mm>>1, chunk half = mm&1.
    int mm    = lane >> 3;
    int ntOff = mm >> 1;
    int halfB = mm & 1;
    int rB    = wn * 32 + (lane & 7) + ntOff * 8;
    int b7    = rB & 7;
    uint32_t bBase[2];
#pragma unroll
    for (int p = 0; p < 2; p++) bBase[p] = sBu + (uint32_t)((rB + p * 16) * 256);

    // ---- mainloop: 8 k-steps, 16 mma each ----
    float d[4][4][4];
#pragma unroll
    for (int mt = 0; mt < 4; mt++)
#pragma unroll
        for (int nt = 0; nt < 4; nt++)
#pragma unroll
            for (int v = 0; v < 4; v++) d[mt][nt][v] = 0.0f;

#pragma unroll
    for (int ks = 0; ks < 8; ks++) {
        uint32_t a[4][4], b[4][2];
#pragma unroll
        for (int mt = 0; mt < 4; mt++) {
            uint32_t addr = aBase[mt] + (uint32_t)((((ks * 2 + halfA) ^ a7)) << 4);
            LDSM_X4(a[mt][0], a[mt][1], a[mt][2], a[mt][3], addr);
        }
#pragma unroll
        for (int p = 0; p < 2; p++) {
            uint32_t addr = bBase[p] + (uint32_t)((((ks * 2 + halfB) ^ b7)) << 4);
            LDSM_X4(b[2 * p][0], b[2 * p][1], b[2 * p + 1][0], b[2 * p + 1][1], addr);
        }
#pragma unroll
        for (int mt = 0; mt < 4; mt++)
#pragma unroll
            for (int nt = 0; nt < 4; nt++)
                MMA_BF16(d[mt][nt], a[mt], b[nt]);
    }

    // ---- fused epilogue: mask diag -> exp -> row reduce -> atomic ----
    // D fragment: thread T holds rows (T/4, T/4+8), cols ((T%4)*2, +1) of each tile.
    int rl = lane >> 2;            // 0..7
    int cl = (lane & 3) * 2;       // 0,2,4,6
    bool md = (mat >= 1);
    int warp_row0 = row0 + wm * 64;
    int warp_col0 = col0 + wn * 32;

#pragma unroll
    for (int mt = 0; mt < 4; mt++) {
        int r_lo = warp_row0 + mt * 16 + rl;
        int r_hi = r_lo + 8;
        float e0 = 0.0f, e1 = 0.0f;
#pragma unroll
        for (int nt = 0; nt < 4; nt++) {
            int n0 = warp_col0 + nt * 8 + cl;
            float v0 = d[mt][nt][0], v1 = d[mt][nt][1];
            float v2 = d[mt][nt][2], v3 = d[mt][nt][3];
            if (md) {
                if (n0     == r_lo) v0 = DELTA_C;
                if (n0 + 1 == r_lo) v1 = DELTA_C;
                if (n0     == r_hi) v2 = DELTA_C;
                if (n0 + 1 == r_hi) v3 = DELTA_C;
            }
            e0 += __expf(v0 * INV_MAG) + __expf(v1 * INV_MAG);
            e1 += __expf(v2 * INV_MAG) + __expf(v3 * INV_MAG);
        }
        // reduce over the 4 lanes holding the same rows (lane%4 group)
        e0 += __shfl_xor_sync(0xffffffffu, e0, 1);
        e0 += __shfl_xor_sync(0xffffffffu, e0, 2);
        e1 += __shfl_xor_sync(0xffffffffu, e1, 1);
        e1 += __shfl_xor_sync(0xffffffffu, e1, 2);
        if ((lane & 3) == 0) {
            atomicAdd(&g_rowsum[r_lo], coef * e0);
            atomicAdd(&g_rowsum[r_hi], coef * e1);
        }
    }
}

// ---------------- finalize ----------------
__global__ __launch_bounds__(256) void finalize_k(const float* __restrict__ A,
                                                  const float* __restrict__ P,
                                                  float* out) {
    int tid = threadIdx.x;
    int row = blockIdx.x * 256 + tid;
    const float4* a4 = (const float4*)(A + (size_t)row * DDIM);
    const float4* p4 = (const float4*)(P + (size_t)row * DDIM);
    float dsum = 0.0f;
#pragma unroll
    for (int k = 0; k < DDIM / 4; k++) {
        float4 a = a4[k], p = p4[k];
        dsum += a.x * p.x + a.y * p.y + a.z * p.z + a.w * p.w;
    }
    float v = logf(g_rowsum[row]) - dsum * INV_MAG;
    v = v > 0.0f ? v : 0.0f;
    __shared__ float sh[256];
    sh[tid] = v;
    __syncthreads();
#pragma unroll
    for (int s = 128; s > 0; s >>= 1) {
        if (tid < s) sh[tid] += sh[tid + s];
        __syncthreads();
    }
    if (tid == 0) atomicAdd(out, sh[0] * (1.0f / NROWS));
}

extern "C" void kernel_launch(void* const* d_in, const int* in_sizes, int n_in,
                              void* d_out, int out_size) {
    const float* A  = (const float*)d_in[0];
    const float* P  = (const float*)d_in[1];
    const float* Ng = (const float*)d_in[2];
    float* out = (float*)d_out;

    static int smem_set = 0;
    if (!smem_set) {
        cudaFuncSetAttribute(gemm_exp_mma, cudaFuncAttributeMaxDynamicSharedMemorySize,
                             2 * TILE * 256);
        smem_set = 1;
    }

    zero_k<<<NROWS / 256, 256>>>(out);
    dim3 cg(NROWS * DDIM / 4 / 256, 3);
    conv_k<<<cg, 256>>>(A, P, Ng);
    dim3 grid(NROWS / TILE, NROWS / TILE, 3);   // (64, 64, 3)
    gemm_exp_mma<<<grid, THREADS, 2 * TILE * 256>>>();
    finalize_k<<<NROWS / 256, 256>>>(A, P, out);
}